// round 8
// baseline (speedup 1.0000x reference)
#include <cuda_runtime.h>

#define GRID_N 32
#define CELLS  1024
#define SROW   24              // smem row stride: 2*SROW % 32 == 16 -> conflict-free
#define NROWS  34
#define NT     256
#define ESW    4

__global__ void __launch_bounds__(NT, 1)
dijkstra_grid_kernel(const float* __restrict__ wg, float* __restrict__ out)
{
    __shared__ float Ea[NROWS * SROW];      // even-x columns
    __shared__ float Oa[NROWS * SROW];      // odd-x columns
    __shared__ unsigned short pred[CELLS];
    __shared__ unsigned char  mark[CELLS];
    __shared__ int flags[3];

    volatile float* E = Ea;
    volatile float* O = Oa;

    const int b  = blockIdx.x;
    const int t  = threadIdx.x;
    const int tx = t & 15;
    const int ty = t >> 4;
    const float INF = __int_as_float(0x7f800000);

    const int x0 = tx * 2, y0 = ty * 2;
    const int rt = y0, ra = y0 + 1, rc = y0 + 2, rb = y0 + 3;

    const float2* w2 = (const float2*)(wg + (size_t)b * CELLS);
    const float2 wAB = w2[y0 * 16 + tx];
    const float2 wCD = w2[(y0 + 1) * 16 + tx];
    const float wa = wAB.x, wb = wAB.y, wc = wCD.x, wd = wCD.y;

    for (int i = t; i < NROWS * SROW; i += NT) { Ea[i] = INF; Oa[i] = INF; }
    for (int i = t; i < CELLS; i += NT) mark[i] = 0;
    if (t < 3) flags[t] = 0;
    __syncthreads();

    float a = (t == 0) ? 0.0f : INF;        // (y0,   x0)
    float bv = INF;                          // (y0,   x0+1)
    float c = INF;                           // (y0+1, x0)
    float d = INF;                           // (y0+1, x0+1)
    Ea[ra * SROW + tx] = a;  Oa[ra * SROW + tx + 1] = bv;
    Ea[rc * SROW + tx] = c;  Oa[rc * SROW + tx + 1] = d;
    __syncthreads();

    // halo loads: 12 conflict-free LDS
    // [0]=tl [1]=tce [2]=tco [3]=tre [4]=bl [5]=bce [6]=bco [7]=bre
    // [8]=l0 [9]=l1 [10]=r0 [11]=r1
#define LOAD_HALOS(H)                                                  \
    do {                                                               \
        (H)[0]  = O[rt * SROW + tx];     (H)[1]  = E[rt * SROW + tx];  \
        (H)[2]  = O[rt * SROW + tx + 1]; (H)[3]  = E[rt * SROW + tx + 1]; \
        (H)[4]  = O[rb * SROW + tx];     (H)[5]  = E[rb * SROW + tx];  \
        (H)[6]  = O[rb * SROW + tx + 1]; (H)[7]  = E[rb * SROW + tx + 1]; \
        (H)[8]  = O[ra * SROW + tx];     (H)[9]  = O[rc * SROW + tx];  \
        (H)[10] = E[ra * SROW + tx + 1]; (H)[11] = E[rc * SROW + tx + 1]; \
    } while (0)

    // ---- chaotic min-plus relaxation: alternating forward/backward GS on
    // the 2x2 register block, Jacobi across blocks through smem. Every
    // candidate is d[nb] + w (RN): exact, monotone-decreasing, reference-
    // attainable path sums; unique fixed point == reference Dijkstra bitwise.
    int e = 0;
    for (;; e++) {
        const float sa = a, sb = bv, sc = c, sd = d;
        float h[2][12];
        LOAD_HALOS(h[0]);
#pragma unroll
        for (int k = 0; k < ESW; k++) {
            const float* H = h[k & 1];
            // off-chain static min trees (halo-only)
            float hA = fminf(fminf(H[0], H[1]), fminf(H[2],  fminf(H[8],  H[9])));
            float hB = fminf(fminf(H[1], H[2]), fminf(H[3],  fminf(H[10], H[11])));
            float hC = fminf(fminf(H[8], H[9]), fminf(H[4],  fminf(H[5],  H[6])));
            float hD = fminf(fminf(H[10],H[11]),fminf(H[5],  fminf(H[6],  H[7])));
            // prefetch next sweep's halos (stale-by-one is valid chaotic relax)
            if (k + 1 < ESW) LOAD_HALOS(h[(k + 1) & 1]);

            if ((k & 1) == 0) {
                // forward GS: a, b, c, d
                a  = fminf(a,  fminf(hA, fminf(fminf(bv, c), d)) + wa);
                bv = fminf(bv, fminf(hB, fminf(a, fminf(c, d))) + wb);
                c  = fminf(c,  fminf(hC, fminf(fminf(a, bv), d)) + wc);
                d  = fminf(d,  fminf(hD, fminf(fminf(a, bv), c)) + wd);
            } else {
                // backward GS: d, c, b, a
                d  = fminf(d,  fminf(hD, fminf(fminf(a, bv), c)) + wd);
                c  = fminf(c,  fminf(hC, fminf(fminf(a, bv), d)) + wc);
                bv = fminf(bv, fminf(hB, fminf(a, fminf(c, d))) + wb);
                a  = fminf(a,  fminf(hA, fminf(fminf(bv, c), d)) + wa);
            }
            E[ra * SROW + tx] = a;  O[ra * SROW + tx + 1] = bv;
            E[rc * SROW + tx] = c;  O[rc * SROW + tx + 1] = d;
        }
        // registers are monotone-decreasing: an epoch with no change anywhere
        // means the global fixed point is reached.
        if ((a != sa) | (bv != sb) | (c != sc) | (d != sd)) flags[e % 3] = 1;
        if (t == 0) flags[(e + 1) % 3] = 0;   // reset ordered by the barriers
        __syncthreads();
        if (!flags[e % 3]) break;             // uniform exit
    }
#undef LOAD_HALOS

    // ---- predecessor = argmin over 8 neighbor distances (unique a.s.) ----
    {
        float tl  = Oa[rt * SROW + tx];
        float tce = Ea[rt * SROW + tx];
        float tco = Oa[rt * SROW + tx + 1];
        float tre = Ea[rt * SROW + tx + 1];
        float bl  = Oa[rb * SROW + tx];
        float bce = Ea[rb * SROW + tx];
        float bco = Oa[rb * SROW + tx + 1];
        float bre = Ea[rb * SROW + tx + 1];
        float l0  = Oa[ra * SROW + tx];
        float l1  = Oa[rc * SROW + tx];
        float r0  = Ea[ra * SROW + tx + 1];
        float r1  = Ea[rc * SROW + tx + 1];

        const int A = y0 * GRID_N + x0, B = A + 1, C = A + GRID_N, D = A + GRID_N + 1;

#define ARGMIN8(v1,i1,v2,i2,v3,i3,v4,i4,v5,i5,v6,i6,v7,i7,v8,i8, OUTCELL)      \
        {                                                                       \
            float bd = INF; int bi = 0;                                         \
            if (v1 < bd) { bd = v1; bi = i1; }                                  \
            if (v2 < bd) { bd = v2; bi = i2; }                                  \
            if (v3 < bd) { bd = v3; bi = i3; }                                  \
            if (v4 < bd) { bd = v4; bi = i4; }                                  \
            if (v5 < bd) { bd = v5; bi = i5; }                                  \
            if (v6 < bd) { bd = v6; bi = i6; }                                  \
            if (v7 < bd) { bd = v7; bi = i7; }                                  \
            if (v8 < bd) { bd = v8; bi = i8; }                                  \
            pred[OUTCELL] = (unsigned short)bi;                                 \
        }

        ARGMIN8(tl, A-33, tce, A-32, tco, A-31, l0, A-1, bv, A+1,
                l1, A+31, c, A+32, d, A+33, A)
        ARGMIN8(tce, B-33, tco, B-32, tre, B-31, a, B-1, r0, B+1,
                c, B+31, d, B+32, r1, B+33, B)
        ARGMIN8(l0, C-33, a, C-32, bv, C-31, l1, C-1, d, C+1,
                bl, C+31, bce, C+32, bco, C+33, C)
        ARGMIN8(a, D-33, bv, D-32, r0, D-31, c, D-1, r1, D+1,
                bce, D+31, bco, D+32, bre, D+33, D)
#undef ARGMIN8
    }
    __syncthreads();

    // ---- backtrack from (31,31); pred chain strictly decreases dist ----
    if (t == 0) {
        int cur = CELLS - 1;
        for (int i = 0; i < CELLS; i++) {
            mark[cur] = 1;
            if (cur == 0) break;
            cur = pred[cur];
        }
    }
    __syncthreads();

    // ---- coalesced float2 output ----
    {
        float2* o2 = (float2*)(out + (size_t)b * CELLS);
        const int A = y0 * GRID_N + x0;
        o2[y0 * 16 + tx]       = make_float2(mark[A]      ? 1.0f : 0.0f,
                                             mark[A + 1]  ? 1.0f : 0.0f);
        o2[(y0 + 1) * 16 + tx] = make_float2(mark[A + 32] ? 1.0f : 0.0f,
                                             mark[A + 33] ? 1.0f : 0.0f);
    }
}

extern "C" void kernel_launch(void* const* d_in, const int* in_sizes, int n_in,
                              void* d_out, int out_size)
{
    const float* w = (const float*)d_in[0];
    float* out = (float*)d_out;
    int batches = in_sizes[0] / CELLS;     // 128
    dijkstra_grid_kernel<<<batches, NT>>>(w, out);
}